// round 3
// baseline (speedup 1.0000x reference)
#include <cuda_runtime.h>
#include <cuda_bf16.h>

// SegEncodeLoss:
//   preds:   [32768, 19] float32
//   targets: [32, 1024, 1024] int32, labels in [0, 19)
//   grid_size = 32 (scalar input, hardcoded)
//   out: scalar float = mean over (32768*19) of BCE(sigmoid(preds), presence)
//
// presence[n, c] = 1 if class c appears in the 32x32 tile n of targets.
// loss element  = softplus(x) - t*x   (stable BCE-with-logits identity)

#define NCLASS 19
#define NBLOCKS 32768

__device__ float g_acc;

__global__ void seg_zero_kernel() { g_acc = 0.0f; }

__global__ __launch_bounds__(256) void seg_loss_kernel(
    const float* __restrict__ preds,
    const int*   __restrict__ targets)
{
    const int warp = (blockIdx.x * blockDim.x + threadIdx.x) >> 5;  // tile id, 0..32767
    const int lane = threadIdx.x & 31;

    // tile id n = b*1024 + hb*32 + wb  (b: batch, hb/wb: 32x32 tile coords)
    const int wb = warp & 31;
    const int hb = (warp >> 5) & 31;
    const int b  = warp >> 10;

    const int* base = targets + ((size_t)b << 20) + ((size_t)(hb << 5)) * 1024 + (wb << 5);

    // Each lane: 4 consecutive labels (int4) per row, covering 8 lanes * 16B = 128B row.
    // Lanes 0-7 -> row r0=0, 8-15 -> row 1, etc. 8 iterations cover 32 rows.
    const int r0 = lane >> 3;
    const int c4 = (lane & 7) << 2;

    unsigned mask = 0u;
    #pragma unroll
    for (int it = 0; it < 8; ++it) {
        const int row = (it << 2) + r0;
        int4 v = *reinterpret_cast<const int4*>(base + row * 1024 + c4);
        mask |= (1u << v.x) | (1u << v.y) | (1u << v.z) | (1u << v.w);
    }
    mask = __reduce_or_sync(0xffffffffu, mask);   // warp-wide presence mask

    float contrib = 0.0f;
    if (lane < NCLASS) {
        const float x  = preds[warp * NCLASS + lane];
        const float sp = fmaxf(x, 0.0f) + log1pf(__expf(-fabsf(x)));  // softplus(x)
        const float t  = (float)((mask >> lane) & 1u);
        contrib = sp - t * x;
    }

    // warp sum
    #pragma unroll
    for (int o = 16; o > 0; o >>= 1)
        contrib += __shfl_down_sync(0xffffffffu, contrib, o);

    __shared__ float ssum[8];
    if (lane == 0) ssum[threadIdx.x >> 5] = contrib;
    __syncthreads();
    if (threadIdx.x == 0) {
        float s = 0.0f;
        #pragma unroll
        for (int i = 0; i < 8; ++i) s += ssum[i];
        atomicAdd(&g_acc, s);
    }
}

__global__ void seg_finalize_kernel(float* __restrict__ out) {
    out[0] = g_acc * (1.0f / (float)(NBLOCKS * NCLASS));
}

extern "C" void kernel_launch(void* const* d_in, const int* in_sizes, int n_in,
                              void* d_out, int out_size)
{
    const float* preds   = (const float*)d_in[0];
    const int*   targets = (const int*)d_in[1];
    float*       out     = (float*)d_out;

    seg_zero_kernel<<<1, 1>>>();
    seg_loss_kernel<<<NBLOCKS / 8, 256>>>(preds, targets);
    seg_finalize_kernel<<<1, 1>>>(out);
}

// round 4
// speedup vs baseline: 1.0748x; 1.0748x over previous
#include <cuda_runtime.h>
#include <cuda_bf16.h>

// SegEncodeLoss:
//   preds:   [32768, 19] float32
//   targets: [32, 1024, 1024] int32, labels in [0, 19)
//   grid_size = 32 (hardcoded)
//   out: scalar float = mean over (32768*19) of BCE(sigmoid(preds), presence)
//
// presence[n, c] = 1 if class c appears in the 32x32 tile n of targets.
// loss element  = softplus(x) - t*x   (stable BCE-with-logits identity)
//
// Structure: 2 launches (main + finalize). The main kernel writes one partial
// sum per CTA into a __device__ array (written every call -> no pre-zero
// kernel needed, fully deterministic). Finalize reduces 4096 partials.

#define NCLASS  19
#define NBLOCKS 32768
#define NCTA    (NBLOCKS / 8)   // 4096 CTAs, 8 warps each, 1 tile per warp

__device__ float g_part[NCTA];

__global__ __launch_bounds__(256) void seg_loss_kernel(
    const float* __restrict__ preds,
    const int*   __restrict__ targets)
{
    const int warp = (blockIdx.x * blockDim.x + threadIdx.x) >> 5;  // tile id
    const int lane = threadIdx.x & 31;

    // tile id n = b*1024 + hb*32 + wb
    const int wb = warp & 31;
    const int hb = (warp >> 5) & 31;
    const int b  = warp >> 10;

    const int* base = targets + ((size_t)b << 20) + ((size_t)(hb << 5)) * 1024 + (wb << 5);

    // Each lane: int4 (4 labels) per row segment; 8 lanes cover the 128B row
    // chunk, 8 iterations x 4 row-groups cover all 32 rows. All 8 loads are
    // independent -> MLP=8 per lane.
    const int r0 = lane >> 3;
    const int c4 = (lane & 7) << 2;

    unsigned mask = 0u;
    #pragma unroll
    for (int it = 0; it < 8; ++it) {
        const int row = (it << 2) + r0;
        int4 v = __ldcs(reinterpret_cast<const int4*>(base + row * 1024 + c4));
        mask |= (1u << v.x) | (1u << v.y) | (1u << v.z) | (1u << v.w);
    }
    mask = __reduce_or_sync(0xffffffffu, mask);   // warp-wide presence mask

    float contrib = 0.0f;
    if (lane < NCLASS) {
        const float x  = __ldg(&preds[warp * NCLASS + lane]);
        const float sp = fmaxf(x, 0.0f) + log1pf(__expf(-fabsf(x)));  // softplus(x)
        const float t  = (float)((mask >> lane) & 1u);
        contrib = sp - t * x;
    }

    // warp sum
    #pragma unroll
    for (int o = 16; o > 0; o >>= 1)
        contrib += __shfl_down_sync(0xffffffffu, contrib, o);

    __shared__ float ssum[8];
    if (lane == 0) ssum[threadIdx.x >> 5] = contrib;
    __syncthreads();
    if (threadIdx.x == 0) {
        float s = 0.0f;
        #pragma unroll
        for (int i = 0; i < 8; ++i) s += ssum[i];
        g_part[blockIdx.x] = s;        // unconditional write: no pre-zero needed
    }
}

__global__ __launch_bounds__(256) void seg_finalize_kernel(float* __restrict__ out)
{
    const int tid = threadIdx.x;
    float s = 0.0f;
    #pragma unroll
    for (int i = 0; i < NCTA / 256; ++i)       // 16 strided elements per thread
        s += g_part[tid + i * 256];

    #pragma unroll
    for (int o = 16; o > 0; o >>= 1)
        s += __shfl_down_sync(0xffffffffu, s, o);

    __shared__ float ssum[8];
    if ((tid & 31) == 0) ssum[tid >> 5] = s;
    __syncthreads();
    if (tid == 0) {
        float tot = 0.0f;
        #pragma unroll
        for (int i = 0; i < 8; ++i) tot += ssum[i];
        out[0] = tot * (1.0f / (float)(NBLOCKS * NCLASS));
    }
}

extern "C" void kernel_launch(void* const* d_in, const int* in_sizes, int n_in,
                              void* d_out, int out_size)
{
    const float* preds   = (const float*)d_in[0];
    const int*   targets = (const int*)d_in[1];
    float*       out     = (float*)d_out;

    seg_loss_kernel<<<NCTA, 256>>>(preds, targets);
    seg_finalize_kernel<<<1, 256>>>(out);
}

// round 7
// speedup vs baseline: 1.0849x; 1.0094x over previous
#include <cuda_runtime.h>
#include <cuda_bf16.h>

// SegEncodeLoss:
//   preds:   [32768, 19] float32
//   targets: [32, 1024, 1024] int32, labels in [0, 19)
//   grid_size = 32 (hardcoded)
//   out: scalar float = mean over (32768*19) of BCE(sigmoid(preds), presence)
//
// presence[n, c] = 1 if class c appears in the 32x32 tile n of targets.
// loss element  = softplus(x) - t*x   (stable BCE-with-logits identity)
//
// Single fused launch: each CTA writes a partial sum; the last CTA to finish
// (tracked via a self-resetting atomicInc counter) reduces all partials and
// writes the scalar. No pre-zero pass, no separate finalize launch.

#define NCLASS  19
#define NBLOCKS 32768
#define NCTA    (NBLOCKS / 8)   // 4096 CTAs, 8 warps each, 1 tile per warp

__device__ float    g_part[NCTA];
__device__ unsigned g_ctr = 0;   // wraps back to 0 every call via atomicInc

__global__ __launch_bounds__(256) void seg_loss_kernel(
    const float* __restrict__ preds,
    const int*   __restrict__ targets,
    float*       __restrict__ out)
{
    const int warp = (blockIdx.x * blockDim.x + threadIdx.x) >> 5;  // tile id
    const int lane = threadIdx.x & 31;

    // tile id n = b*1024 + hb*32 + wb
    const int wb = warp & 31;
    const int hb = (warp >> 5) & 31;
    const int b  = warp >> 10;

    const int* base = targets + ((size_t)b << 20) + ((size_t)(hb << 5)) * 1024 + (wb << 5);

    // Each lane: int4 (4 labels) per row segment; 8 lanes cover the 128B row
    // chunk, 8 iterations x 4 row-groups cover all 32 rows. All 8 loads are
    // independent -> MLP=8 per lane.
    const int r0 = lane >> 3;
    const int c4 = (lane & 7) << 2;

    unsigned mask = 0u;
    #pragma unroll
    for (int it = 0; it < 8; ++it) {
        const int row = (it << 2) + r0;
        int4 v = __ldcs(reinterpret_cast<const int4*>(base + row * 1024 + c4));
        mask |= (1u << v.x) | (1u << v.y) | (1u << v.z) | (1u << v.w);
    }
    mask = __reduce_or_sync(0xffffffffu, mask);   // warp-wide presence mask

    float contrib = 0.0f;
    if (lane < NCLASS) {
        const float x  = __ldg(&preds[warp * NCLASS + lane]);
        const float sp = fmaxf(x, 0.0f) + log1pf(__expf(-fabsf(x)));  // softplus(x)
        const float t  = (float)((mask >> lane) & 1u);
        contrib = sp - t * x;
    }

    // warp sum
    #pragma unroll
    for (int o = 16; o > 0; o >>= 1)
        contrib += __shfl_down_sync(0xffffffffu, contrib, o);

    __shared__ float ssum[8];
    __shared__ bool  s_last;
    if (lane == 0) ssum[threadIdx.x >> 5] = contrib;
    __syncthreads();

    if (threadIdx.x == 0) {
        float s = 0.0f;
        #pragma unroll
        for (int i = 0; i < 8; ++i) s += ssum[i];
        g_part[blockIdx.x] = s;
        __threadfence();                              // partial visible before count
        unsigned old = atomicInc(&g_ctr, NCTA - 1);   // wraps to 0 after NCTA-th
        s_last = (old == NCTA - 1);
    }
    __syncthreads();

    if (s_last) {
        // Last CTA: reduce all 4096 partials (L2-resident). 16 loads/thread.
        __threadfence();   // acquire: see all g_part writes
        const int tid = threadIdx.x;
        float s = 0.0f;
        #pragma unroll
        for (int i = 0; i < NCTA / 256; ++i)
            s += g_part[tid + i * 256];

        #pragma unroll
        for (int o = 16; o > 0; o >>= 1)
            s += __shfl_down_sync(0xffffffffu, s, o);

        if (lane == 0) ssum[tid >> 5] = s;
        __syncthreads();
        if (tid == 0) {
            float tot = 0.0f;
            #pragma unroll
            for (int i = 0; i < 8; ++i) tot += ssum[i];
            out[0] = tot * (1.0f / (float)(NBLOCKS * NCLASS));
        }
    }
}

extern "C" void kernel_launch(void* const* d_in, const int* in_sizes, int n_in,
                              void* d_out, int out_size)
{
    const float* preds   = (const float*)d_in[0];
    const int*   targets = (const int*)d_in[1];
    float*       out     = (float*)d_out;

    seg_loss_kernel<<<NCTA, 256>>>(preds, targets, out);
}